// round 1
// baseline (speedup 1.0000x reference)
#include <cuda_runtime.h>

// out[b] = -(inp[b,:] . quad)^2 + inp[b,:] . linw + bias
// B = 16384, D = 4096, fp32. Pure streaming-read problem: 256 MiB of inp.
//
// Strategy: warp-per-row, weights staged in SMEM once per block (32 rows/block)
// so weight re-reads never hit L2/DRAM. Lanes load consecutive float4 ->
// perfectly coalesced 512B per warp access.

#ifndef D_DIM
#define D_DIM 4096
#endif

constexpr int THREADS        = 256;   // 8 warps
constexpr int ROWS_PER_WARP  = 4;
constexpr int WARPS          = THREADS / 32;
constexpr int ROWS_PER_BLOCK = WARPS * ROWS_PER_WARP;  // 32
constexpr int D4             = D_DIM / 4;              // 1024 float4 per row
constexpr int F4_PER_LANE    = D4 / 32;                // 32 float4 per lane per row

__global__ __launch_bounds__(THREADS)
void skinny_quad_kernel(const float* __restrict__ inp,
                        const float* __restrict__ quad,
                        const float* __restrict__ linw,
                        const float* __restrict__ linb,
                        float* __restrict__ out,
                        int B)
{
    __shared__ float4 s_wq[D4];
    __shared__ float4 s_wl[D4];

    const int tid  = threadIdx.x;
    const int lane = tid & 31;
    const int warp = tid >> 5;

    // Stage weights into SMEM (each thread copies D4/THREADS = 4 float4 per array)
    const float4* gq = reinterpret_cast<const float4*>(quad);
    const float4* gl = reinterpret_cast<const float4*>(linw);
    #pragma unroll
    for (int i = tid; i < D4; i += THREADS) {
        s_wq[i] = gq[i];
        s_wl[i] = gl[i];
    }
    const float bias = *linb;
    __syncthreads();

    const int row0 = blockIdx.x * ROWS_PER_BLOCK + warp * ROWS_PER_WARP;

    #pragma unroll
    for (int r = 0; r < ROWS_PER_WARP; ++r) {
        const int row = row0 + r;
        if (row >= B) break;

        const float4* __restrict__ xr =
            reinterpret_cast<const float4*>(inp + (size_t)row * D_DIM);

        float sq = 0.f;
        float sl = 0.f;

        #pragma unroll 8
        for (int i = 0; i < F4_PER_LANE; ++i) {
            const int idx = lane + i * 32;     // lanes -> consecutive float4
            const float4 x = xr[idx];
            const float4 q = s_wq[idx];
            const float4 l = s_wl[idx];
            sq = fmaf(x.x, q.x, sq);
            sq = fmaf(x.y, q.y, sq);
            sq = fmaf(x.z, q.z, sq);
            sq = fmaf(x.w, q.w, sq);
            sl = fmaf(x.x, l.x, sl);
            sl = fmaf(x.y, l.y, sl);
            sl = fmaf(x.z, l.z, sl);
            sl = fmaf(x.w, l.w, sl);
        }

        // warp reduction of the (sq, sl) pair
        #pragma unroll
        for (int off = 16; off > 0; off >>= 1) {
            sq += __shfl_down_sync(0xFFFFFFFFu, sq, off);
            sl += __shfl_down_sync(0xFFFFFFFFu, sl, off);
        }

        if (lane == 0) {
            out[row] = fmaf(-sq, sq, sl + bias);
        }
    }
}

extern "C" void kernel_launch(void* const* d_in, const int* in_sizes, int n_in,
                              void* d_out, int out_size)
{
    const float* inp  = (const float*)d_in[0];   // (B, D)
    const float* quad = (const float*)d_in[1];   // (D, 1) contiguous D floats
    const float* linw = (const float*)d_in[2];   // (1, D) contiguous D floats
    const float* linb = (const float*)d_in[3];   // (1,)
    float* out = (float*)d_out;

    const int B = in_sizes[0] / D_DIM;
    const int grid = (B + ROWS_PER_BLOCK - 1) / ROWS_PER_BLOCK;

    skinny_quad_kernel<<<grid, THREADS>>>(inp, quad, linw, linb, out, B);
}